// round 11
// baseline (speedup 1.0000x reference)
#include <cuda_runtime.h>
#include <cooperative_groups.h>
#include <math.h>

namespace cg = cooperative_groups;

#define D       256    // feature dim (fixed)
#define NT      256    // threads per block
#define NWARP   8
#define SROWS   16     // rows per pipeline stage (16 KB)
#define NSTAGE  3      // triple buffer
#define SPLIT   2      // blocks per segment == cluster size

// Load segment id at index i, supporting int64 or int32 storage.
__device__ __forceinline__ long long load_seg(const void* seg, int i, bool is64) {
    if (is64) return ((const long long*)seg)[i];
    return (long long)((const int*)seg)[i];
}

// Issue one stage copy (rows * 1KB) as a single cp.async group. rows may be <=0.
__device__ __forceinline__ void issue_stage(float* dst, const float* src, int rows, int tid) {
    unsigned ds = (unsigned)__cvta_generic_to_shared(dst);
    if (rows == SROWS) {                        // fast path: fully unrolled
        const float* s = src + tid * 4;
        unsigned d = ds + tid * 16;
        #pragma unroll
        for (int k = 0; k < 4; k++)
            asm volatile("cp.async.cg.shared.global [%0], [%1], 16;"
                         :: "r"(d + k * NT * 16), "l"(s + k * NT * 4));
    } else {
        const int chunks = rows * (D / 4);      // rows<=0 -> no copies
        for (int c = tid; c < chunks; c += NT)
            asm volatile("cp.async.cg.shared.global [%0], [%1], 16;"
                         :: "r"(ds + c * 16), "l"(src + c * 4));
    }
    asm volatile("cp.async.commit_group;");     // always commit (keeps FIFO depth exact)
}

__global__ __launch_bounds__(NT) __cluster_dims__(SPLIT, 1, 1)
void gap_compute(
    const float* __restrict__ feat,     // [N, D]
    const float* __restrict__ Wg,       // [D]
    const float* __restrict__ bg,       // [1]
    const void*  __restrict__ seg,      // [N] sorted
    int N,
    float* __restrict__ out)            // [B, D]
{
    __shared__ __align__(16) float sBuf[NSTAGE][SROWS * D];   // 48 KB ring
    __shared__ __align__(16) float sW[D];
    __shared__ float sS[NWARP];
    __shared__ int   sLB[2];            // [0]=lower_bound(b), [1]=lower_bound(b+1)
    __shared__ __align__(16) float sOut[D + 4];   // per-block partial: 256 cols + sum

    cg::cluster_group cluster = cg::this_cluster();

    const int blk  = blockIdx.x;
    const int b    = blk / SPLIT;
    const int half = blk % SPLIT;       // == cluster rank
    const int tid  = threadIdx.x;
    const int warp = tid >> 5;
    const int lane = tid & 31;

    sW[tid] = Wg[tid];
    const float bias = bg[0];

    // dtype sniff: int64 ids (< 2^31) have zero high word at the tail; int32 doesn't.
    const bool is64 = (((const int*)seg)[N - 1] == 0);

    // ---- warp-cooperative 32-ary lower_bound: warp w searches value b+w.
    if (warp < 2) {
        const long long x = (long long)b + warp;
        int lo = 0, W = N + 1;          // lower_bound may be N
        while (W > 1) {
            const int i = lo + (int)(((long long)W * lane) >> 5);
            const bool pred = (i < N) && (load_seg(seg, i, is64) < x);
            const unsigned bal = __ballot_sync(0xffffffffu, pred);
            const int c = __popc(bal);
            const int nlo = (c == 0)  ? lo     : lo + (int)(((long long)W * (c - 1)) >> 5) + 1;
            const int nhi = (c == 32) ? lo + W : lo + (int)(((long long)W * c) >> 5) + 1;
            lo = nlo; W = nhi - nlo;
        }
        if (lane == 0) sLB[warp] = lo;
    }
    __syncthreads();                    // sW + sLB visible

    const int start = sLB[0];
    const int cnt   = sLB[1] - start;

    // this block's sub-range of the segment (may be empty -> zero partial below)
    const int r0   = start + (cnt * half) / SPLIT;
    const int r1   = start + (cnt * (half + 1)) / SPLIT;
    const int scnt = r1 - r0;

    const float4 w0 = ((const float4*)sW)[lane];
    const float4 w1 = ((const float4*)sW)[lane + 32];

    float ssum = 0.0f;
    float acc[8];
    #pragma unroll
    for (int j = 0; j < 8; j++) acc[j] = 0.0f;

    const float* fbase   = feat + (size_t)r0 * D;
    const int    nstages = (scnt + SROWS - 1) / SROWS;   // 0 if empty

    // prologue: stages 0 and 1 in flight (rows<=0 -> empty committed group)
    issue_stage(sBuf[0], fbase, min(SROWS, scnt), tid);
    issue_stage(sBuf[1], fbase + (size_t)SROWS * D, min(SROWS, scnt - SROWS), tid);

    for (int s = 0; s < nstages; s++) {
        asm volatile("cp.async.wait_group 1;"); // stage s landed
        __syncthreads();   // single bar: stage s visible AND slot (s+2)%3 free

        const int rnext = (s + 2) * SROWS;
        issue_stage(sBuf[(s + 2) % NSTAGE], fbase + (size_t)rnext * D,
                    min(SROWS, scnt - rnext), tid);

        const int    rows = min(SROWS, scnt - s * SROWS);
        const float* buf  = sBuf[s % NSTAGE];

        const bool v0 = (warp         < rows);
        const bool v1 = (warp + NWARP < rows);
        const float* p0 = buf + (v0 ? warp           * D : 0);   // safe fallback row 0
        const float* p1 = buf + (v1 ? (warp + NWARP) * D : 0);
        float4 a0 = ((const float4*)p0)[lane];
        float4 a1 = ((const float4*)p0)[lane + 32];
        float4 c0 = ((const float4*)p1)[lane];
        float4 c1 = ((const float4*)p1)[lane + 32];

        float s0 = a0.x*w0.x + a0.y*w0.y + a0.z*w0.z + a0.w*w0.w
                 + a1.x*w1.x + a1.y*w1.y + a1.z*w1.z + a1.w*w1.w;
        float s1 = c0.x*w0.x + c0.y*w0.y + c0.z*w0.z + c0.w*w0.w
                 + c1.x*w1.x + c1.y*w1.y + c1.z*w1.z + c1.w*w1.w;
        #pragma unroll
        for (int o = 16; o > 0; o >>= 1) {
            s0 += __shfl_xor_sync(0xffffffffu, s0, o);
            s1 += __shfl_xor_sync(0xffffffffu, s1, o);
        }
        // softmax is shift-invariant -> no max subtraction (gates ~ N(0,1))
        const float e0 = v0 ? __expf(s0 + bias) : 0.0f;
        const float e1 = v1 ? __expf(s1 + bias) : 0.0f;
        ssum += e0 + e1;
        acc[0] += e0*a0.x + e1*c0.x;
        acc[1] += e0*a0.y + e1*c0.y;
        acc[2] += e0*a0.z + e1*c0.z;
        acc[3] += e0*a0.w + e1*c0.w;
        acc[4] += e0*a1.x + e1*c1.x;
        acc[5] += e0*a1.y + e1*c1.y;
        acc[6] += e0*a1.z + e1*c1.z;
        acc[7] += e0*a1.w + e1*c1.w;
    }

    // -------- additive cross-warp merge (reuse stage buffer 0 as merge area)
    asm volatile("cp.async.wait_group 0;");     // drain tail (empty) groups
    __syncthreads();                            // all warps done reading sBuf
    float* sAcc = sBuf[0];
    if (lane == 0) sS[warp] = ssum;
    ((float4*)(sAcc + warp * D))[lane]      = make_float4(acc[0], acc[1], acc[2], acc[3]);
    ((float4*)(sAcc + warp * D))[lane + 32] = make_float4(acc[4], acc[5], acc[6], acc[7]);
    __syncthreads();

    float v = 0.0f;
    #pragma unroll
    for (int w = 0; w < NWARP; w++) v += sAcc[w * D + tid];
    sOut[tid] = v;
    if (tid == 0) {
        float tot = 0.0f;
        #pragma unroll
        for (int w = 0; w < NWARP; w++) tot += sS[w];
        sOut[256] = tot;
    }

    // -------- cluster-pair finalize: both ranks read peer partial via DSMEM
    cluster.sync();                     // both blocks' sOut published

    float* peer = cluster.map_shared_rank(sOut, half ^ 1);
    if (tid < 128) {
        const int   col = half * 128 + tid;       // this rank writes its half-row
        const float ps  = peer[256];
        const float ss  = sOut[256] + ps;         // fp add commutative -> deterministic
        const float val = sOut[col] + peer[col];
        out[(size_t)b * D + col] = (ss > 0.0f) ? val / ss : 0.0f;   // empty -> 0
    }

    cluster.sync();                     // keep peer smem alive during reads
}

extern "C" void kernel_launch(void* const* d_in, const int* in_sizes, int n_in,
                              void* d_out, int out_size) {
    const float* feat = (const float*)d_in[0];
    const float* Wg   = (const float*)d_in[1];
    const float* bg   = (const float*)d_in[2];
    const void*  seg  = d_in[3];
    const int N = in_sizes[0] / D;
    const int B = out_size / D;
    gap_compute<<<B * SPLIT, NT>>>(feat, Wg, bg, seg, N, (float*)d_out);
}

// round 12
// speedup vs baseline: 1.0274x; 1.0274x over previous
#include <cuda_runtime.h>
#include <math.h>

#define D       256    // feature dim (fixed)
#define NT      256    // threads per block
#define NWARP   8
#define SROWS   16     // rows per pipeline stage (16 KB)
#define NSTAGE  3      // triple buffer
#define SPLIT   2      // blocks per segment
#define PSTRIDE 264    // floats per partial row (256 acc + 1 sum + pad)

__device__ float g_partial[2048 * PSTRIDE];   // partial accumulators
__device__ int   g_count[1024];               // per-segment arrival counters (self-reset)

// Load segment id at index i, supporting int64 or int32 storage.
__device__ __forceinline__ long long load_seg(const void* seg, int i, bool is64) {
    if (is64) return ((const long long*)seg)[i];
    return (long long)((const int*)seg)[i];
}

// acq_rel gpu-scope fetch-add: release publishes prior writes, acquire imports peers'.
__device__ __forceinline__ int atom_inc_acqrel(int* p) {
    int old;
    asm volatile("atom.add.acq_rel.gpu.global.s32 %0, [%1], 1;"
                 : "=r"(old) : "l"(p) : "memory");
    return old;
}

// Issue one stage copy (rows * 1KB) as a single cp.async group. rows may be <=0.
__device__ __forceinline__ void issue_stage(float* dst, const float* src, int rows, int tid) {
    unsigned ds = (unsigned)__cvta_generic_to_shared(dst);
    if (rows == SROWS) {                        // fast path: fully unrolled
        const float* s = src + tid * 4;
        unsigned d = ds + tid * 16;
        #pragma unroll
        for (int k = 0; k < 4; k++)
            asm volatile("cp.async.cg.shared.global [%0], [%1], 16;"
                         :: "r"(d + k * NT * 16), "l"(s + k * NT * 4));
    } else {
        const int chunks = rows * (D / 4);      // rows<=0 -> no copies
        for (int c = tid; c < chunks; c += NT)
            asm volatile("cp.async.cg.shared.global [%0], [%1], 16;"
                         :: "r"(ds + c * 16), "l"(src + c * 4));
    }
    asm volatile("cp.async.commit_group;");     // always commit (keeps FIFO depth exact)
}

__global__ __launch_bounds__(NT) void gap_compute(
    const float* __restrict__ feat,     // [N, D]
    const float* __restrict__ Wg,       // [D]
    const float* __restrict__ bg,       // [1]
    const void*  __restrict__ seg,      // [N] sorted
    int N,
    float* __restrict__ out)            // [B, D]
{
    __shared__ __align__(16) float sBuf[NSTAGE][SROWS * D];   // 48 KB ring
    __shared__ __align__(16) float sW[D];
    __shared__ float sS[NWARP];
    __shared__ int   sLB[2];            // [0]=lower_bound(b), [1]=lower_bound(b+1)
    __shared__ int   sLast;

    const int blk  = blockIdx.x;
    const int b    = blk / SPLIT;
    const int half = blk % SPLIT;
    const int tid  = threadIdx.x;
    const int warp = tid >> 5;
    const int lane = tid & 31;

    sW[tid] = Wg[tid];
    const float bias = bg[0];

    // dtype sniff: int64 ids (< 2^31) have zero high word at the tail; int32 doesn't.
    const bool is64 = (((const int*)seg)[N - 1] == 0);

    // ---- warp-cooperative 32-ary lower_bound: warp w searches value b+w.
    if (warp < 2) {
        const long long x = (long long)b + warp;
        int lo = 0, W = N + 1;          // lower_bound may be N
        while (W > 1) {
            const int i = lo + (int)(((long long)W * lane) >> 5);
            const bool pred = (i < N) && (load_seg(seg, i, is64) < x);
            const unsigned bal = __ballot_sync(0xffffffffu, pred);
            const int c = __popc(bal);
            const int nlo = (c == 0)  ? lo     : lo + (int)(((long long)W * (c - 1)) >> 5) + 1;
            const int nhi = (c == 32) ? lo + W : lo + (int)(((long long)W * c) >> 5) + 1;
            lo = nlo; W = nhi - nlo;
        }
        if (lane == 0) sLB[warp] = lo;
    }
    __syncthreads();                    // sW + sLB visible

    const int start = sLB[0];
    const int cnt   = sLB[1] - start;

    // this block's sub-range of the segment (may be empty -> zero partial)
    const int r0   = start + (cnt * half) / SPLIT;
    const int r1   = start + (cnt * (half + 1)) / SPLIT;
    const int scnt = r1 - r0;

    const float4 w0 = ((const float4*)sW)[lane];
    const float4 w1 = ((const float4*)sW)[lane + 32];

    float ssum = 0.0f;
    float acc[8];
    #pragma unroll
    for (int j = 0; j < 8; j++) acc[j] = 0.0f;

    const float* fbase   = feat + (size_t)r0 * D;
    const int    nstages = (scnt + SROWS - 1) / SROWS;   // 0 if empty

    // prologue: stages 0 and 1 in flight (rows<=0 -> empty committed group)
    issue_stage(sBuf[0], fbase, min(SROWS, scnt), tid);
    issue_stage(sBuf[1], fbase + (size_t)SROWS * D, min(SROWS, scnt - SROWS), tid);

    for (int s = 0; s < nstages; s++) {
        asm volatile("cp.async.wait_group 1;"); // stage s landed
        __syncthreads();   // single bar: stage s visible AND slot (s+2)%3 free

        const int rnext = (s + 2) * SROWS;
        issue_stage(sBuf[(s + 2) % NSTAGE], fbase + (size_t)rnext * D,
                    min(SROWS, scnt - rnext), tid);

        const int    rows = min(SROWS, scnt - s * SROWS);
        const float* buf  = sBuf[s % NSTAGE];

        const bool v0 = (warp         < rows);
        const bool v1 = (warp + NWARP < rows);
        const float* p0 = buf + (v0 ? warp           * D : 0);   // safe fallback row 0
        const float* p1 = buf + (v1 ? (warp + NWARP) * D : 0);
        float4 a0 = ((const float4*)p0)[lane];
        float4 a1 = ((const float4*)p0)[lane + 32];
        float4 c0 = ((const float4*)p1)[lane];
        float4 c1 = ((const float4*)p1)[lane + 32];

        float s0 = a0.x*w0.x + a0.y*w0.y + a0.z*w0.z + a0.w*w0.w
                 + a1.x*w1.x + a1.y*w1.y + a1.z*w1.z + a1.w*w1.w;
        float s1 = c0.x*w0.x + c0.y*w0.y + c0.z*w0.z + c0.w*w0.w
                 + c1.x*w1.x + c1.y*w1.y + c1.z*w1.z + c1.w*w1.w;
        #pragma unroll
        for (int o = 16; o > 0; o >>= 1) {
            s0 += __shfl_xor_sync(0xffffffffu, s0, o);
            s1 += __shfl_xor_sync(0xffffffffu, s1, o);
        }
        // softmax is shift-invariant -> no max subtraction (gates ~ N(0,1))
        const float e0 = v0 ? __expf(s0 + bias) : 0.0f;
        const float e1 = v1 ? __expf(s1 + bias) : 0.0f;
        ssum += e0 + e1;
        acc[0] += e0*a0.x + e1*c0.x;
        acc[1] += e0*a0.y + e1*c0.y;
        acc[2] += e0*a0.z + e1*c0.z;
        acc[3] += e0*a0.w + e1*c0.w;
        acc[4] += e0*a1.x + e1*c1.x;
        acc[5] += e0*a1.y + e1*c1.y;
        acc[6] += e0*a1.z + e1*c1.z;
        acc[7] += e0*a1.w + e1*c1.w;
    }

    // -------- additive cross-warp merge (reuse stage buffer 0 as merge area)
    asm volatile("cp.async.wait_group 0;");     // drain tail (empty) groups
    __syncthreads();                            // all warps done reading sBuf
    float* sAcc = sBuf[0];
    if (lane == 0) sS[warp] = ssum;
    ((float4*)(sAcc + warp * D))[lane]      = make_float4(acc[0], acc[1], acc[2], acc[3]);
    ((float4*)(sAcc + warp * D))[lane + 32] = make_float4(acc[4], acc[5], acc[6], acc[7]);
    __syncthreads();

    float v = 0.0f;
    #pragma unroll
    for (int w = 0; w < NWARP; w++) v += sAcc[w * D + tid];
    float tot = 0.0f;
    #pragma unroll
    for (int w = 0; w < NWARP; w++) tot += sS[w];

    // -------- publish partial; last-arriving block of the pair finalizes
    float* part = g_partial + (size_t)blk * PSTRIDE;
    part[tid] = v;
    if (tid == 0) part[256] = tot;
    __syncthreads();                    // all partial stores ordered before the atomic
    if (tid == 0) {
        const int old = atom_inc_acqrel(&g_count[b]);   // release: partial published
        sLast = (old == SPLIT - 1);
    }
    __syncthreads();

    if (sLast) {
        if (tid == 0) g_count[b] = 0;   // self-reset for next graph replay
        const float* peer = g_partial + (size_t)(b * SPLIT + (1 - half)) * PSTRIDE;
        const float pv = __ldcg(peer + tid);    // L2-resident (just written)
        const float ps = __ldcg(peer + 256);
        // canonical half0 + half1 order -> bitwise-identical output every call
        const float vh0 = half ? pv  : v;
        const float vh1 = half ? v   : pv;
        const float sh0 = half ? ps  : tot;
        const float sh1 = half ? tot : ps;
        const float ss  = sh0 + sh1;
        out[(size_t)b * D + tid] = (ss > 0.0f) ? (vh0 + vh1) / ss : 0.0f;  // empty -> 0
    }
}

extern "C" void kernel_launch(void* const* d_in, const int* in_sizes, int n_in,
                              void* d_out, int out_size) {
    const float* feat = (const float*)d_in[0];
    const float* Wg   = (const float*)d_in[1];
    const float* bg   = (const float*)d_in[2];
    const void*  seg  = d_in[3];
    const int N = in_sizes[0] / D;
    const int B = out_size / D;
    gap_compute<<<B * SPLIT, NT>>>(feat, Wg, bg, seg, N, (float*)d_out);
}

// round 15
// speedup vs baseline: 1.1253x; 1.0953x over previous
#include <cuda_runtime.h>
#include <math.h>

#define D       256    // feature dim (fixed)
#define NT      256    // threads per block
#define NWARP   8
#define SROWS   16     // rows per pipeline stage (16 KB)
#define NSTAGE  3      // triple buffer

// Load segment id at index i, supporting int64 or int32 storage.
__device__ __forceinline__ long long load_seg(const void* seg, int i, bool is64) {
    if (is64) return ((const long long*)seg)[i];
    return (long long)((const int*)seg)[i];
}

// Issue one stage copy (rows * 1KB) as a single cp.async group. rows may be <=0.
__device__ __forceinline__ void issue_stage(float* dst, const float* src, int rows, int tid) {
    unsigned ds = (unsigned)__cvta_generic_to_shared(dst);
    if (rows == SROWS) {                        // fast path: fully unrolled
        const float* s = src + tid * 4;
        unsigned d = ds + tid * 16;
        #pragma unroll
        for (int k = 0; k < 4; k++)
            asm volatile("cp.async.cg.shared.global [%0], [%1], 16;"
                         :: "r"(d + k * NT * 16), "l"(s + k * NT * 4));
    } else {
        const int chunks = rows * (D / 4);      // rows<=0 -> no copies
        for (int c = tid; c < chunks; c += NT)
            asm volatile("cp.async.cg.shared.global [%0], [%1], 16;"
                         :: "r"(ds + c * 16), "l"(src + c * 4));
    }
    asm volatile("cp.async.commit_group;");     // always commit (keeps FIFO depth exact)
}

__global__ __launch_bounds__(NT) void gap_compute(
    const float* __restrict__ feat,     // [N, D]
    const float* __restrict__ Wg,       // [D]
    const float* __restrict__ bg,       // [1]
    const void*  __restrict__ seg,      // [N] sorted
    int N,
    float* __restrict__ out)            // [B, D]
{
    __shared__ __align__(16) float sBuf[NSTAGE][SROWS * D];   // 48 KB ring
    __shared__ __align__(16) float sW[D];
    __shared__ float sS[NWARP];
    __shared__ int   sLB[2];            // [0]=lower_bound(b), [1]=lower_bound(b+1)

    const int b    = blockIdx.x;        // one block per segment
    const int tid  = threadIdx.x;
    const int warp = tid >> 5;
    const int lane = tid & 31;

    sW[tid] = Wg[tid];
    const float bias = bg[0];

    // dtype sniff: int64 ids (< 2^31) have zero high word at the tail; int32 doesn't.
    const bool is64 = (((const int*)seg)[N - 1] == 0);

    // ---- warp-cooperative 32-ary lower_bound: warp w searches value b+w.
    if (warp < 2) {
        const long long x = (long long)b + warp;
        int lo = 0, W = N + 1;          // lower_bound may be N
        while (W > 1) {
            const int i = lo + (int)(((long long)W * lane) >> 5);
            const bool pred = (i < N) && (load_seg(seg, i, is64) < x);
            const unsigned bal = __ballot_sync(0xffffffffu, pred);
            const int c = __popc(bal);
            const int nlo = (c == 0)  ? lo     : lo + (int)(((long long)W * (c - 1)) >> 5) + 1;
            const int nhi = (c == 32) ? lo + W : lo + (int)(((long long)W * c) >> 5) + 1;
            lo = nlo; W = nhi - nlo;
        }
        if (lane == 0) sLB[warp] = lo;
    }
    __syncthreads();                    // sW + sLB visible

    const int start = sLB[0];
    const int cnt   = sLB[1] - start;   // may be 0 (empty segment)

    const float4 w0 = ((const float4*)sW)[lane];
    const float4 w1 = ((const float4*)sW)[lane + 32];

    float ssum = 0.0f;
    float acc[8];
    #pragma unroll
    for (int j = 0; j < 8; j++) acc[j] = 0.0f;

    const float* fbase   = feat + (size_t)start * D;
    const int    nstages = (cnt + SROWS - 1) / SROWS;    // 0 if empty

    // prologue: stages 0 and 1 in flight (rows<=0 -> empty committed group)
    issue_stage(sBuf[0], fbase, min(SROWS, cnt), tid);
    issue_stage(sBuf[1], fbase + (size_t)SROWS * D, min(SROWS, cnt - SROWS), tid);

    for (int s = 0; s < nstages; s++) {
        asm volatile("cp.async.wait_group 1;"); // stage s landed
        __syncthreads();   // single bar: stage s visible AND slot (s+2)%3 free

        const int rnext = (s + 2) * SROWS;
        issue_stage(sBuf[(s + 2) % NSTAGE], fbase + (size_t)rnext * D,
                    min(SROWS, cnt - rnext), tid);

        const int    rows = min(SROWS, cnt - s * SROWS);
        const float* buf  = sBuf[s % NSTAGE];

        const bool v0 = (warp         < rows);
        const bool v1 = (warp + NWARP < rows);
        const float* p0 = buf + (v0 ? warp           * D : 0);   // safe fallback row 0
        const float* p1 = buf + (v1 ? (warp + NWARP) * D : 0);
        float4 a0 = ((const float4*)p0)[lane];
        float4 a1 = ((const float4*)p0)[lane + 32];
        float4 c0 = ((const float4*)p1)[lane];
        float4 c1 = ((const float4*)p1)[lane + 32];

        float s0 = a0.x*w0.x + a0.y*w0.y + a0.z*w0.z + a0.w*w0.w
                 + a1.x*w1.x + a1.y*w1.y + a1.z*w1.z + a1.w*w1.w;
        float s1 = c0.x*w0.x + c0.y*w0.y + c0.z*w0.z + c0.w*w0.w
                 + c1.x*w1.x + c1.y*w1.y + c1.z*w1.z + c1.w*w1.w;
        #pragma unroll
        for (int o = 16; o > 0; o >>= 1) {
            s0 += __shfl_xor_sync(0xffffffffu, s0, o);
            s1 += __shfl_xor_sync(0xffffffffu, s1, o);
        }
        // softmax is shift-invariant -> no max subtraction (gates ~ N(0,1))
        const float e0 = v0 ? __expf(s0 + bias) : 0.0f;
        const float e1 = v1 ? __expf(s1 + bias) : 0.0f;
        ssum += e0 + e1;
        acc[0] += e0*a0.x + e1*c0.x;
        acc[1] += e0*a0.y + e1*c0.y;
        acc[2] += e0*a0.z + e1*c0.z;
        acc[3] += e0*a0.w + e1*c0.w;
        acc[4] += e0*a1.x + e1*c1.x;
        acc[5] += e0*a1.y + e1*c1.y;
        acc[6] += e0*a1.z + e1*c1.z;
        acc[7] += e0*a1.w + e1*c1.w;
    }

    // -------- additive cross-warp merge (reuse stage buffer 0 as merge area)
    asm volatile("cp.async.wait_group 0;");     // drain tail (empty) groups
    __syncthreads();                            // all warps done reading sBuf
    float* sAcc = sBuf[0];
    if (lane == 0) sS[warp] = ssum;
    ((float4*)(sAcc + warp * D))[lane]      = make_float4(acc[0], acc[1], acc[2], acc[3]);
    ((float4*)(sAcc + warp * D))[lane + 32] = make_float4(acc[4], acc[5], acc[6], acc[7]);
    __syncthreads();

    float v = 0.0f;
    #pragma unroll
    for (int w = 0; w < NWARP; w++) v += sAcc[w * D + tid];
    float tot = 0.0f;
    #pragma unroll
    for (int w = 0; w < NWARP; w++) tot += sS[w];

    // single-owner finalize: no partials, no second kernel
    out[(size_t)b * D + tid] = (tot > 0.0f) ? v / tot : 0.0f;   // empty segment -> 0
}

extern "C" void kernel_launch(void* const* d_in, const int* in_sizes, int n_in,
                              void* d_out, int out_size) {
    const float* feat = (const float*)d_in[0];
    const float* Wg   = (const float*)d_in[1];
    const float* bg   = (const float*)d_in[2];
    const void*  seg  = d_in[3];
    const int N = in_sizes[0] / D;
    const int B = out_size / D;
    gap_compute<<<B, NT>>>(feat, Wg, bg, seg, N, (float*)d_out);
}